// round 2
// baseline (speedup 1.0000x reference)
#include <cuda_runtime.h>
#include <math.h>

#define BT 192
#define NSEQ 207
#define CDIM 128
#define RED 64
#define DIN 128
#define DS 16
#define NTOK (BT*NSEQ)   // 39744

// scratch (device globals; no allocation allowed)
__device__ float g_h[NTOK*RED];          // ~10.2 MB
__device__ float g_y[2][NTOK*RED];       // ~20.3 MB

// ---------------------------------------------------------------------------
// Kernel 1: h = LN256(concat(x,qk)) @ in_w + in_b   -> g_h (192*207, 64)
// ---------------------------------------------------------------------------
__global__ __launch_bounds__(256) void k1_ln_inproj(
    const float* __restrict__ x, const float* __restrict__ qk,
    const float* __restrict__ lnw, const float* __restrict__ lnb,
    const float* __restrict__ w, const float* __restrict__ b)
{
  __shared__ float sn[256];
  __shared__ float part[256];
  __shared__ float red[16];
  __shared__ float mv[2];
  int tid = threadIdx.x;
  int j = tid & 63, q = tid >> 6;
  float wr[64];
  #pragma unroll
  for (int i = 0; i < 64; i++) wr[i] = w[(q*64+i)*64 + j];
  float lw = lnw[tid], lb = lnb[tid];
  int base = blockIdx.x * 32;
  for (int it = 0; it < 32; it++) {
    int tok = base + it;
    float v = (tid < 128) ? x[tok*128 + tid] : qk[tok*128 + tid - 128];
    float s = v, s2 = v*v;
    #pragma unroll
    for (int o = 16; o; o >>= 1) {
      s  += __shfl_xor_sync(~0u, s,  o);
      s2 += __shfl_xor_sync(~0u, s2, o);
    }
    int wid = tid >> 5;
    if ((tid & 31) == 0) { red[wid] = s; red[8+wid] = s2; }
    __syncthreads();
    if (tid == 0) {
      float ts = 0.f, ts2 = 0.f;
      #pragma unroll
      for (int k2 = 0; k2 < 8; k2++) { ts += red[k2]; ts2 += red[8+k2]; }
      float m = ts * (1.f/256.f);
      float var = ts2 * (1.f/256.f) - m*m;
      mv[0] = m; mv[1] = rsqrtf(var + 1e-5f);
    }
    __syncthreads();
    float m = mv[0], rs = mv[1];
    sn[tid] = (v - m) * rs * lw + lb;
    __syncthreads();
    float acc = 0.f;
    const float4* s4 = (const float4*)&sn[q*64];
    #pragma unroll
    for (int i = 0; i < 16; i++) {
      float4 hv = s4[i];
      acc += hv.x*wr[4*i] + hv.y*wr[4*i+1] + hv.z*wr[4*i+2] + hv.w*wr[4*i+3];
    }
    part[tid] = acc;
    __syncthreads();
    if (tid < 64) {
      float o = part[tid] + part[64+tid] + part[128+tid] + part[192+tid] + b[tid];
      g_h[tok*64 + tid] = o;
    }
    __syncthreads();
  }
}

// ---------------------------------------------------------------------------
// Kernel 2: full Mamba pass for one (sequence, direction).
// grid (192, 2), 512 threads, ~207 KB dynamic smem.
// ---------------------------------------------------------------------------
#define SM_H   0                 // 207*64  = 13248
#define SM_U   13248             // 207*128 = 26496
#define SM_DT  39744             // 207*4   = 828
#define SM_B   40572             // 207*16  = 3312
#define SM_Cc  43884             // 207*16  = 3312
#define SM_XPT 47196             // 36*129  = 4644
#define SM_TOTF (SM_XPT + 36*129)          // 51840 floats
#define SM_BYTES (SM_TOTF * 4)             // 207360 bytes

extern __shared__ float sm2[];

__device__ __forceinline__ float softplus_f(float xv) {
  return (xv > 15.f) ? xv : log1pf(__expf(xv));
}

__global__ __launch_bounds__(512) void k2_mamba(
  const float* __restrict__ ip0, const float* __restrict__ cw0, const float* __restrict__ cb0,
  const float* __restrict__ xp0, const float* __restrict__ dw0, const float* __restrict__ db0,
  const float* __restrict__ al0, const float* __restrict__ dp0, const float* __restrict__ op0,
  const float* __restrict__ ip1, const float* __restrict__ cw1, const float* __restrict__ cb1,
  const float* __restrict__ xp1, const float* __restrict__ dw1, const float* __restrict__ db1,
  const float* __restrict__ al1, const float* __restrict__ dp1, const float* __restrict__ op1)
{
  float* sm = sm2;
  int seq = blockIdx.x;
  int dir = blockIdx.y;
  const float* inproj  = dir ? ip1 : ip0;
  const float* convw   = dir ? cw1 : cw0;
  const float* convb   = dir ? cb1 : cb0;
  const float* xproj   = dir ? xp1 : xp0;
  const float* dtw     = dir ? dw1 : dw0;
  const float* dtb     = dir ? db1 : db0;
  const float* Alog    = dir ? al1 : al0;
  const float* Dp      = dir ? dp1 : dp0;
  const float* outproj = dir ? op1 : op0;
  int tid = threadIdx.x;

  // ---- Phase A: load h (time-reversed for bw) + xproj (transposed, padded) ----
  for (int idx = tid; idx < NSEQ*16; idx += 512) {       // 3312 float4
    int t = idx >> 4, k4 = idx & 15;
    int tt = dir ? (NSEQ-1-t) : t;
    ((float4*)sm)[idx] = ((const float4*)(g_h + (seq*NSEQ + tt)*64))[k4];
  }
  for (int idx = tid; idx < DIN*36; idx += 512) {
    int d = idx / 36, jj = idx % 36;
    sm[SM_XPT + jj*129 + d] = xproj[idx];
  }
  __syncthreads();

  // ---- Phase B: u_raw = h @ inproj[:, :128] ----
  {
    int d = tid & 127, q = tid >> 7;
    float wu[64];
    #pragma unroll
    for (int i = 0; i < 64; i++) wu[i] = inproj[i*256 + d];
    for (int t = q; t < NSEQ; t += 4) {
      const float4* h4 = (const float4*)&sm[SM_H + t*64];
      float acc = 0.f;
      #pragma unroll
      for (int i = 0; i < 16; i++) {
        float4 hv = h4[i];
        acc += hv.x*wu[4*i] + hv.y*wu[4*i+1] + hv.z*wu[4*i+2] + hv.w*wu[4*i+3];
      }
      sm[SM_U + t*128 + d] = acc;
    }
  }
  __syncthreads();

  // ---- Phase C: causal conv (K=4) + silu, in place, descending t (safe) ----
  if (tid < 128) {
    int d = tid;
    float c0 = convw[d*4+0], c1 = convw[d*4+1], c2 = convw[d*4+2], c3 = convw[d*4+3];
    float cb = convb[d];
    for (int t = NSEQ-1; t >= 0; t--) {
      float s = cb + sm[SM_U + t*128 + d]*c3;
      if (t >= 1) s += sm[SM_U + (t-1)*128 + d]*c2;
      if (t >= 2) s += sm[SM_U + (t-2)*128 + d]*c1;
      if (t >= 3) s += sm[SM_U + (t-3)*128 + d]*c0;
      s = s / (1.f + __expf(-s));          // silu
      sm[SM_U + t*128 + d] = s;
    }
  }
  __syncthreads();

  // ---- Phase D: xdbl = u @ xproj  -> dt-pre(4), B(16), C(16) ----
  if (tid < 504) {
    int jj = tid % 36, tl = tid / 36;      // tl 0..13
    float acc[15];
    #pragma unroll
    for (int i = 0; i < 15; i++) acc[i] = 0.f;
    for (int dc = 0; dc < 128; dc += 32) {
      float wr[32];
      #pragma unroll
      for (int i = 0; i < 32; i++) wr[i] = sm[SM_XPT + jj*129 + dc + i];
      #pragma unroll
      for (int tt = 0; tt < 15; tt++) {
        int t = tl + tt*14;
        if (t < NSEQ) {
          const float4* u4 = (const float4*)&sm[SM_U + t*128 + dc];
          float a = 0.f;
          #pragma unroll
          for (int i = 0; i < 8; i++) {
            float4 uv = u4[i];
            a += uv.x*wr[4*i] + uv.y*wr[4*i+1] + uv.z*wr[4*i+2] + uv.w*wr[4*i+3];
          }
          acc[tt] += a;
        }
      }
    }
    #pragma unroll
    for (int tt = 0; tt < 15; tt++) {
      int t = tl + tt*14;
      if (t < NSEQ) {
        float v = acc[tt];
        if (jj < 4)       sm[SM_DT + t*4  + jj]      = v;
        else if (jj < 20) sm[SM_B  + t*16 + (jj-4)]  = v;
        else              sm[SM_Cc + t*16 + (jj-20)] = v;
      }
    }
  }
  __syncthreads();

  // ---- Phase E: selective scan. 4 lanes per channel (n-split), butterfly y. ----
  {
    int p = tid & 3, d = tid >> 2;
    float Ar[4], hs[4] = {0.f,0.f,0.f,0.f};
    #pragma unroll
    for (int i = 0; i < 4; i++) Ar[i] = -__expf(Alog[d*16 + p*4 + i]);
    float w0 = dtw[0*128+d], w1 = dtw[1*128+d], w2 = dtw[2*128+d], w3 = dtw[3*128+d];
    float dbr = dtb[d];
    float Dr = Dp[d];
    for (int t = 0; t < NSEQ; t++) {
      float4 dq = *(const float4*)&sm[SM_DT + t*4];
      float xdt = dbr + dq.x*w0 + dq.y*w1 + dq.z*w2 + dq.w*w3;
      float dt = softplus_f(xdt);
      float u = sm[SM_U + t*128 + d];
      float du = dt * u;
      float4 Bv = *(const float4*)&sm[SM_B  + t*16 + p*4];
      float4 Cv = *(const float4*)&sm[SM_Cc + t*16 + p*4];
      float e0 = __expf(dt*Ar[0]); hs[0] = hs[0]*e0 + du*Bv.x; float y = hs[0]*Cv.x;
      float e1 = __expf(dt*Ar[1]); hs[1] = hs[1]*e1 + du*Bv.y; y += hs[1]*Cv.y;
      float e2 = __expf(dt*Ar[2]); hs[2] = hs[2]*e2 + du*Bv.z; y += hs[2]*Cv.z;
      float e3 = __expf(dt*Ar[3]); hs[3] = hs[3]*e3 + du*Bv.w; y += hs[3]*Cv.w;
      y += __shfl_xor_sync(~0u, y, 1);
      y += __shfl_xor_sync(~0u, y, 2);
      if (p == 0) sm[SM_U + t*128 + d] = y + u*Dr;   // y_pre, overwrites u
    }
  }
  __syncthreads();

  // ---- Phase F: gate: y *= silu(z), z = h @ inproj[:, 128:256] ----
  {
    int d = tid & 127, q = tid >> 7;
    float wz[64];
    #pragma unroll
    for (int i = 0; i < 64; i++) wz[i] = inproj[i*256 + 128 + d];
    for (int t = q; t < NSEQ; t += 4) {
      const float4* h4 = (const float4*)&sm[SM_H + t*64];
      float z = 0.f;
      #pragma unroll
      for (int i = 0; i < 16; i++) {
        float4 hv = h4[i];
        z += hv.x*wz[4*i] + hv.y*wz[4*i+1] + hv.z*wz[4*i+2] + hv.w*wz[4*i+3];
      }
      float g = z / (1.f + __expf(-z));
      sm[SM_U + t*128 + d] *= g;
    }
  }
  __syncthreads();

  // ---- Phase G: out = y @ outproj (128x64) -> g_y[dir] (un-reversed) ----
  {
    int j = tid & 63, tl = tid >> 6;       // tl 0..7
    for (int half = 0; half < 2; half++) {
      float acc[13];
      #pragma unroll
      for (int i = 0; i < 13; i++) acc[i] = 0.f;
      for (int dc = 0; dc < 128; dc += 32) {
        float wr[32];
        #pragma unroll
        for (int i = 0; i < 32; i++) wr[i] = outproj[(dc+i)*64 + j];
        #pragma unroll
        for (int tt = 0; tt < 13; tt++) {
          int t = tl + (half*13 + tt)*8;
          if (t < NSEQ) {
            const float4* y4 = (const float4*)&sm[SM_U + t*128 + dc];
            float a = 0.f;
            #pragma unroll
            for (int i = 0; i < 8; i++) {
              float4 yv = y4[i];
              a += yv.x*wr[4*i] + yv.y*wr[4*i+1] + yv.z*wr[4*i+2] + yv.w*wr[4*i+3];
            }
            acc[tt] += a;
          }
        }
      }
      #pragma unroll
      for (int tt = 0; tt < 13; tt++) {
        int t = tl + (half*13 + tt)*8;
        if (t < NSEQ) {
          int torig = dir ? (NSEQ-1-t) : t;
          g_y[dir][(seq*NSEQ + torig)*64 + j] = acc[tt];
        }
      }
    }
  }
}

// ---------------------------------------------------------------------------
// Kernel 3: yc = fw+bw; LN64 -> @ov_w + ov_b; + x residual; LN128 -> @o_w + o_b
// ---------------------------------------------------------------------------
__global__ __launch_bounds__(256) void k3_out(
  const float* __restrict__ x,
  const float* __restrict__ ovlnw, const float* __restrict__ ovlnb,
  const float* __restrict__ ovw, const float* __restrict__ ovb,
  const float* __restrict__ olnw, const float* __restrict__ olnb,
  const float* __restrict__ ow, const float* __restrict__ ob,
  float* __restrict__ out)
{
  __shared__ float syn[32*64];
  __shared__ float sr[32*128];
  int tid = threadIdx.x;
  int lane = tid & 31, wid = tid >> 5;
  int base = blockIdx.x * 32;
  int kh = tid & 1, c = tid >> 1;
  float ovr[32], owr[64];
  #pragma unroll
  for (int i = 0; i < 32; i++) ovr[i] = ovw[(kh*32+i)*128 + c];
  #pragma unroll
  for (int i = 0; i < 64; i++) owr[i] = ow[(kh*64+i)*128 + c];
  float ovbc = ovb[c], obc = ob[c];

  // LN64 over fw+bw: one warp per token
  for (int r = 0; r < 4; r++) {
    int tl = r*8 + wid;
    int tok = base + tl;
    float v0 = g_y[0][tok*64 + lane]      + g_y[1][tok*64 + lane];
    float v1 = g_y[0][tok*64 + 32 + lane] + g_y[1][tok*64 + 32 + lane];
    float s = v0 + v1, s2 = v0*v0 + v1*v1;
    #pragma unroll
    for (int o = 16; o; o >>= 1) {
      s  += __shfl_xor_sync(~0u, s,  o);
      s2 += __shfl_xor_sync(~0u, s2, o);
    }
    float m = s * (1.f/64.f);
    float rs = rsqrtf(s2 * (1.f/64.f) - m*m + 1e-5f);
    syn[tl*64 + lane]      = (v0 - m)*rs*ovlnw[lane]    + ovlnb[lane];
    syn[tl*64 + 32 + lane] = (v1 - m)*rs*ovlnw[32+lane] + ovlnb[32+lane];
  }
  __syncthreads();

  // ov matmul + residual
  for (int tl = 0; tl < 32; tl++) {
    int tok = base + tl;
    float acc = 0.f;
    const float* sy = &syn[tl*64 + kh*32];
    #pragma unroll
    for (int i = 0; i < 32; i++) acc += sy[i]*ovr[i];
    acc += __shfl_xor_sync(~0u, acc, 1);
    if (kh == 0) sr[tl*128 + c] = acc + ovbc + x[tok*128 + c];
  }
  __syncthreads();

  // LN128: one warp per token, normalize in place
  for (int r = 0; r < 4; r++) {
    int tl = r*8 + wid;
    float v[4]; float s = 0.f, s2 = 0.f;
    #pragma unroll
    for (int i = 0; i < 4; i++) {
      v[i] = sr[tl*128 + i*32 + lane];
      s += v[i]; s2 += v[i]*v[i];
    }
    #pragma unroll
    for (int o = 16; o; o >>= 1) {
      s  += __shfl_xor_sync(~0u, s,  o);
      s2 += __shfl_xor_sync(~0u, s2, o);
    }
    float m = s * (1.f/128.f);
    float rs = rsqrtf(s2 * (1.f/128.f) - m*m + 1e-5f);
    #pragma unroll
    for (int i = 0; i < 4; i++) {
      int k = i*32 + lane;
      sr[tl*128 + k] = (v[i] - m)*rs*olnw[k] + olnb[k];
    }
  }
  __syncthreads();

  // final o matmul
  for (int tl = 0; tl < 32; tl++) {
    int tok = base + tl;
    float acc = 0.f;
    const float* sv = &sr[tl*128 + kh*64];
    #pragma unroll
    for (int i = 0; i < 64; i++) acc += sv[i]*owr[i];
    acc += __shfl_xor_sync(~0u, acc, 1);
    if (kh == 0) out[tok*128 + c] = acc + obc;
  }
}

// ---------------------------------------------------------------------------
extern "C" void kernel_launch(void* const* d_in, const int* in_sizes, int n_in,
                              void* d_out, int out_size) {
  const float* x      = (const float*)d_in[0];
  const float* qk     = (const float*)d_in[1];
  const float* in_lnw = (const float*)d_in[2];
  const float* in_lnb = (const float*)d_in[3];
  const float* in_w   = (const float*)d_in[4];
  const float* in_b   = (const float*)d_in[5];

  const float *fw[9], *bw[9];
  const float *ovlnw, *ovlnb, *ovw, *ovb, *olnw, *olnb, *ow, *ob;

  // Disambiguate input ordering at runtime:
  //  - setup_inputs dict order: d_in[6] = ov_ln_w (64 elems)
  //  - reference signature order: d_in[6] = fw_inproj (64*256 = 16384 elems)
  if (in_sizes[6] == 64 && in_sizes[14] == 16384) {
    // dict-insertion order
    ovlnw = (const float*)d_in[6];  ovlnb = (const float*)d_in[7];
    ovw   = (const float*)d_in[8];  ovb   = (const float*)d_in[9];
    olnw  = (const float*)d_in[10]; olnb  = (const float*)d_in[11];
    ow    = (const float*)d_in[12]; ob    = (const float*)d_in[13];
    for (int i = 0; i < 9; i++) {
      fw[i] = (const float*)d_in[14 + i];
      bw[i] = (const float*)d_in[23 + i];
    }
  } else {
    // reference signature order
    for (int i = 0; i < 9; i++) {
      fw[i] = (const float*)d_in[6 + i];
      bw[i] = (const float*)d_in[15 + i];
    }
    ovlnw = (const float*)d_in[24]; ovlnb = (const float*)d_in[25];
    ovw   = (const float*)d_in[26]; ovb   = (const float*)d_in[27];
    olnw  = (const float*)d_in[28]; olnb  = (const float*)d_in[29];
    ow    = (const float*)d_in[30]; ob    = (const float*)d_in[31];
  }
  float* out = (float*)d_out;

  cudaFuncSetAttribute(k2_mamba, cudaFuncAttributeMaxDynamicSharedMemorySize, SM_BYTES);

  k1_ln_inproj<<<NTOK/32, 256>>>(x, qk, in_lnw, in_lnb, in_w, in_b);

  k2_mamba<<<dim3(BT, 2), 512, SM_BYTES>>>(
      fw[0], fw[1], fw[2], fw[3], fw[4], fw[5], fw[6], fw[7], fw[8],
      bw[0], bw[1], bw[2], bw[3], bw[4], bw[5], bw[6], bw[7], bw[8]);

  k3_out<<<NTOK/32, 256>>>(x, ovlnw, ovlnb, ovw, ovb, olnw, olnb, ow, ob, out);
}